// round 4
// baseline (speedup 1.0000x reference)
#include <cuda_runtime.h>
#include <math.h>
#include <stdint.h>

// Problem constants
#define Nn   32
#define Cc   64
#define Tt   64
#define Vv   204
#define Hh   3
#define QKd  16
#define Pp   13056
#define OQKV 96
#define HC   192

// ---------------- scratch ----------------
__device__ float d_h   [(size_t)Nn * Cc * Pp];     // gcn conv out; later z
__device__ float d_g   [(size_t)Nn * Cc * Pp];
__device__ float d_qk  [(size_t)Nn * OQKV * Pp];
__device__ float d_wpe [(size_t)OQKV * Pp];
__device__ float d_att [(size_t)Nn * Hh * Tt * Tt];
__device__ float d_attp[(size_t)2 * Nn * Hh * Tt * Tt];
__device__ float d_G2  [(size_t)Nn * HC * Pp];     // on_w-transformed g
__device__ float d_w2  [HC * Cc];                  // permuted on_w

enum { MODE_BIAS = 0, MODE_ADD2D = 1, MODE_BN_RES_LEAKY = 2, MODE_NONE = 3 };

// ---------------- helpers ----------------
__device__ __forceinline__ unsigned cvt_tf32(float f) {
    unsigned u;
    asm("cvt.rna.tf32.f32 %0, %1;" : "=r"(u) : "f"(f));
    return u;
}

__device__ __forceinline__ void mma8(float* d, const unsigned* a, const unsigned* b) {
    asm volatile(
        "mma.sync.aligned.m16n8k8.row.col.f32.tf32.tf32.f32 "
        "{%0,%1,%2,%3},{%4,%5,%6,%7},{%8,%9},{%0,%1,%2,%3};"
        : "+f"(d[0]), "+f"(d[1]), "+f"(d[2]), "+f"(d[3])
        : "r"(a[0]), "r"(a[1]), "r"(a[2]), "r"(a[3]), "r"(b[0]), "r"(b[1]));
}

__device__ __forceinline__ void cpa16(uint32_t dst, const void* src) {
    asm volatile("cp.async.cg.shared.global [%0],[%1],16;" :: "r"(dst), "l"(src));
}
__device__ __forceinline__ void cpa16z(uint32_t dst, const void* src, int sz) {
    asm volatile("cp.async.cg.shared.global [%0],[%1],16,%2;" :: "r"(dst), "l"(src), "r"(sz));
}
#define CP_COMMIT() asm volatile("cp.async.commit_group;")
#define CP_WAIT0()  asm volatile("cp.async.wait_group 0;")
#define CP_WAIT1()  asm volatile("cp.async.wait_group 1;")

// ============================================================================
// conv_mma: out[n,o,p] = sum_c W[o,c]*in[n,c,p]
// CTA tile: M=64 (Oc), N=256 (P), k-chunk 16, double-buffered cp.async.
// ============================================================================
template <int MODE>
__global__ __launch_bounds__(256, 2)
void conv_mma(const float* __restrict__ in, const float* __restrict__ W,
              const float* __restrict__ bias, const float* __restrict__ add2d,
              const float* __restrict__ res,
              const float* __restrict__ bng, const float* __restrict__ bnb,
              const float* __restrict__ bnm, const float* __restrict__ bnv,
              float* __restrict__ out, int Kc, int Oc)
{
    __shared__ float As[2][64][20];
    __shared__ float Bs[2][16][264];

    const int n  = blockIdx.z;
    const int pt = blockIdx.x * 256;
    const int ot = blockIdx.y * 64;
    const int tid = threadIdx.x, lane = tid & 31, warp = tid >> 5;
    const int wm = warp & 1, wn = warp >> 1;
    const int m0 = wm * 32, n0 = wn * 64;
    const int lr = lane >> 2, kc = lane & 3;

    const float* inN = in + (size_t)n * Kc * Pp + pt;
    const int wm_row = tid >> 2;
    const int wgrp   = tid & 3;

    float acc[2][8][4];
    #pragma unroll
    for (int f = 0; f < 2; f++)
        #pragma unroll
        for (int j = 0; j < 8; j++)
            #pragma unroll
            for (int q = 0; q < 4; q++) acc[f][j][q] = 0.f;

    const int nchunks = Kc / 16;
    uint4 wreg;

    {
        #pragma unroll
        for (int i = 0; i < 4; i++) {
            int e = tid + 256 * i;
            int k = e >> 6, grp = e & 63;
            cpa16((uint32_t)__cvta_generic_to_shared(&Bs[0][k][grp * 4]),
                  inN + (size_t)k * Pp + grp * 4);
        }
        CP_COMMIT();
        int o = ot + wm_row;
        float4 w = (o < Oc) ? *(const float4*)(W + (size_t)o * Kc + wgrp * 4)
                            : make_float4(0.f, 0.f, 0.f, 0.f);
        wreg = make_uint4(cvt_tf32(w.x), cvt_tf32(w.y), cvt_tf32(w.z), cvt_tf32(w.w));
        *(uint4*)&As[0][wm_row][wgrp * 4] = wreg;
    }

    for (int c = 0; c < nchunks; c++) {
        const int buf = c & 1;
        if (c + 1 < nchunks) {
            const float* base = inN + (size_t)(c + 1) * 16 * Pp;
            #pragma unroll
            for (int i = 0; i < 4; i++) {
                int e = tid + 256 * i;
                int k = e >> 6, grp = e & 63;
                cpa16((uint32_t)__cvta_generic_to_shared(&Bs[buf ^ 1][k][grp * 4]),
                      base + (size_t)k * Pp + grp * 4);
            }
            CP_COMMIT();
            int o = ot + wm_row;
            float4 w = (o < Oc) ? *(const float4*)(W + (size_t)o * Kc + (c + 1) * 16 + wgrp * 4)
                                : make_float4(0.f, 0.f, 0.f, 0.f);
            wreg = make_uint4(cvt_tf32(w.x), cvt_tf32(w.y), cvt_tf32(w.z), cvt_tf32(w.w));
            CP_WAIT1();
        } else {
            CP_WAIT0();
        }
        __syncthreads();

        #pragma unroll
        for (int g = 0; g < 2; g++) {
            unsigned a[2][4];
            #pragma unroll
            for (int f = 0; f < 2; f++) {
                a[f][0] = __float_as_uint(As[buf][m0 + f * 16 + lr    ][g * 8 + kc    ]);
                a[f][1] = __float_as_uint(As[buf][m0 + f * 16 + lr + 8][g * 8 + kc    ]);
                a[f][2] = __float_as_uint(As[buf][m0 + f * 16 + lr    ][g * 8 + kc + 4]);
                a[f][3] = __float_as_uint(As[buf][m0 + f * 16 + lr + 8][g * 8 + kc + 4]);
            }
            #pragma unroll
            for (int j = 0; j < 8; j++) {
                unsigned b[2];
                b[0] = __float_as_uint(Bs[buf][g * 8 + kc    ][n0 + 8 * j + lr]);
                b[1] = __float_as_uint(Bs[buf][g * 8 + kc + 4][n0 + 8 * j + lr]);
                mma8(acc[0][j], a[0], b);
                mma8(acc[1][j], a[1], b);
            }
        }
        __syncthreads();
        if (c + 1 < nchunks)
            *(uint4*)&As[buf ^ 1][wm_row][wgrp * 4] = wreg;
    }

    #pragma unroll
    for (int f = 0; f < 2; f++) {
        #pragma unroll
        for (int half = 0; half < 2; half++) {
            int o = ot + m0 + f * 16 + lr + half * 8;
            if (o >= Oc) continue;
            size_t obase = ((size_t)n * Oc + o) * Pp;
            if (MODE == MODE_NONE) {
                #pragma unroll
                for (int j = 0; j < 8; j++) {
                    int p = pt + n0 + 8 * j + 2 * kc;
                    *(float2*)(out + obase + p) =
                        make_float2(acc[f][j][half * 2], acc[f][j][half * 2 + 1]);
                }
            } else if (MODE == MODE_BIAS) {
                float b = bias[o];
                #pragma unroll
                for (int j = 0; j < 8; j++) {
                    int p = pt + n0 + 8 * j + 2 * kc;
                    *(float2*)(out + obase + p) =
                        make_float2(acc[f][j][half * 2] + b, acc[f][j][half * 2 + 1] + b);
                }
            } else if (MODE == MODE_ADD2D) {
                size_t abase = (size_t)o * Pp;
                #pragma unroll
                for (int j = 0; j < 8; j++) {
                    int p = pt + n0 + 8 * j + 2 * kc;
                    float2 av = *(const float2*)(add2d + abase + p);
                    *(float2*)(out + obase + p) =
                        make_float2(acc[f][j][half * 2] + av.x, acc[f][j][half * 2 + 1] + av.y);
                }
            } else {
                float s  = bng[o] * rsqrtf(bnv[o] + 1e-5f);
                float sh = bnb[o] - bnm[o] * s + bias[o] * s;
                #pragma unroll
                for (int j = 0; j < 8; j++) {
                    int p = pt + n0 + 8 * j + 2 * kc;
                    float2 rv = *(const float2*)(res + obase + p);
                    float va = acc[f][j][half * 2]     * s + sh + rv.x;
                    float vb = acc[f][j][half * 2 + 1] * s + sh + rv.y;
                    *(float2*)(out + obase + p) =
                        make_float2(va > 0.f ? va : 0.1f * va, vb > 0.f ? vb : 0.1f * vb);
                }
            }
        }
    }
}

// ============================================================================
// adj_mma (unchanged): g[r,u] = relu(bn_c(sum_v h[r,v]*A[u,v]) + x[r,u])
// ============================================================================
__global__ __launch_bounds__(256, 2)
void adj_mma(const float* __restrict__ h, const float* __restrict__ Am,
             const float* __restrict__ x,
             const float* __restrict__ bng, const float* __restrict__ bnb,
             const float* __restrict__ bnm, const float* __restrict__ bnv,
             float* __restrict__ out)
{
    __shared__ float As[2][64][20];
    __shared__ float Bs[2][208][20];

    const int rt = blockIdx.x * 64;
    const int tid = threadIdx.x, lane = tid & 31, warp = tid >> 5;
    const int wm = warp & 3, wn = warp >> 2;
    const int m0 = wm * 16, nb0 = wn * 104;
    const int lr = lane >> 2, kc = lane & 3;

    const int ch  = (rt >> 6) & 63;
    const float s  = bng[ch] * rsqrtf(bnv[ch] + 1e-5f);
    const float sh = bnb[ch] - bnm[ch] * s;

    float acc[13][4];
    #pragma unroll
    for (int j = 0; j < 13; j++)
        #pragma unroll
        for (int q = 0; q < 4; q++) acc[j][q] = 0.f;

    const int am = tid >> 2;
    const int aks = (tid & 3) * 4;
    const int NCH = 13;
    uint4 areg;

    {
        #pragma unroll
        for (int i = 0; i < 4; i++) {
            int e = tid + 256 * i;
            if (e < 832) {
                int u = e >> 2, grp = e & 3;
                int v0 = grp * 4;
                int ok = (u < 204 && v0 < 204);
                cpa16z((uint32_t)__cvta_generic_to_shared(&Bs[0][u][grp * 4]),
                       ok ? (Am + (size_t)u * 204 + v0) : Am, ok ? 16 : 0);
            }
        }
        CP_COMMIT();
        float v4[4];
        #pragma unroll
        for (int i = 0; i < 4; i++) {
            int v = aks + i;
            v4[i] = (v < 204) ? h[(size_t)(rt + am) * 204 + v] : 0.f;
        }
        areg = make_uint4(cvt_tf32(v4[0]), cvt_tf32(v4[1]), cvt_tf32(v4[2]), cvt_tf32(v4[3]));
        *(uint4*)&As[0][am][aks] = areg;
    }

    for (int c = 0; c < NCH; c++) {
        const int buf = c & 1;
        if (c + 1 < NCH) {
            int vb = (c + 1) * 16;
            #pragma unroll
            for (int i = 0; i < 4; i++) {
                int e = tid + 256 * i;
                if (e < 832) {
                    int u = e >> 2, grp = e & 3;
                    int v0 = vb + grp * 4;
                    int ok = (u < 204 && v0 < 204);
                    cpa16z((uint32_t)__cvta_generic_to_shared(&Bs[buf ^ 1][u][grp * 4]),
                           ok ? (Am + (size_t)u * 204 + v0) : Am, ok ? 16 : 0);
                }
            }
            CP_COMMIT();
            float v4[4];
            #pragma unroll
            for (int i = 0; i < 4; i++) {
                int v = vb + aks + i;
                v4[i] = (v < 204) ? h[(size_t)(rt + am) * 204 + v] : 0.f;
            }
            areg = make_uint4(cvt_tf32(v4[0]), cvt_tf32(v4[1]), cvt_tf32(v4[2]), cvt_tf32(v4[3]));
            CP_WAIT1();
        } else {
            CP_WAIT0();
        }
        __syncthreads();

        #pragma unroll
        for (int g = 0; g < 2; g++) {
            unsigned a[4];
            a[0] = __float_as_uint(As[buf][m0 + lr    ][g * 8 + kc    ]);
            a[1] = __float_as_uint(As[buf][m0 + lr + 8][g * 8 + kc    ]);
            a[2] = __float_as_uint(As[buf][m0 + lr    ][g * 8 + kc + 4]);
            a[3] = __float_as_uint(As[buf][m0 + lr + 8][g * 8 + kc + 4]);
            #pragma unroll
            for (int j = 0; j < 13; j++) {
                unsigned b[2];
                b[0] = __float_as_uint(Bs[buf][nb0 + 8 * j + lr][g * 8 + kc    ]);
                b[1] = __float_as_uint(Bs[buf][nb0 + 8 * j + lr][g * 8 + kc + 4]);
                mma8(acc[j], a, b);
            }
        }
        __syncthreads();
        if (c + 1 < NCH)
            *(uint4*)&As[buf ^ 1][am][aks] = areg;
    }

    #pragma unroll
    for (int half = 0; half < 2; half++) {
        int r = rt + m0 + lr + half * 8;
        size_t rbase = (size_t)r * 204;
        #pragma unroll
        for (int j = 0; j < 13; j++) {
            int u = nb0 + 8 * j + 2 * kc;
            if (u < 204) {
                float2 xv = *(const float2*)(x + rbase + u);
                float va = acc[j][half * 2]     * s + sh + xv.x;
                float vb = acc[j][half * 2 + 1] * s + sh + xv.y;
                *(float2*)(out + rbase + u) = make_float2(fmaxf(va, 0.f), fmaxf(vb, 0.f));
            }
        }
    }
}

// ============================================================================
// z_mma: z[n,c,q,v] = leaky(bn_c( sum_{s,t} G2[n,s,c,t,v]*att[n,s,t,q] ) + g)
// One CTA per (c, n). M=64(q), N=208(v), K=192 in 3 s-chunks of 64(t).
// ============================================================================
__global__ __launch_bounds__(256)
void z_mma(const float* __restrict__ G2, const float* __restrict__ att,
           const float* __restrict__ g,
           const float* __restrict__ on_b, const float* __restrict__ on_g,
           const float* __restrict__ on_bb, const float* __restrict__ on_m,
           const float* __restrict__ on_v,
           float* __restrict__ out)
{
    extern __shared__ float sm[];
    float (*As)[72]  = (float(*)[72])sm;               // att [k(t)][m(q)]
    float (*Bs)[232] = (float(*)[232])(sm + 64 * 72);  // G2  [k(t)][n(v)]

    const int cch = blockIdx.x, n = blockIdx.y;
    const int tid = threadIdx.x, lane = tid & 31, warp = tid >> 5;
    const int wm = warp & 3, wn = warp >> 2;
    const int m0 = wm * 16, nb0 = wn * 104;
    const int lr = lane >> 2, kc = lane & 3;

    float acc[13][4];
    #pragma unroll
    for (int j = 0; j < 13; j++)
        #pragma unroll
        for (int q = 0; q < 4; q++) acc[j][q] = 0.f;

    for (int s = 0; s < Hh; s++) {
        const float* gb   = G2 + ((size_t)n * HC + s * 64 + cch) * Pp;
        const float* attB = att + (size_t)(n * Hh + s) * 4096;

        #pragma unroll
        for (int i = 0; i < 13; i++) {
            int e = tid + 256 * i;
            if (e < 3328) {
                int t = e / 52, grp = e % 52;
                int ok = (grp < 51);
                cpa16z((uint32_t)__cvta_generic_to_shared(&Bs[t][grp * 4]),
                       ok ? (gb + (size_t)t * 204 + grp * 4) : gb, ok ? 16 : 0);
            }
        }
        CP_COMMIT();
        #pragma unroll
        for (int i = 0; i < 4; i++) {
            int e = tid + 256 * i;
            int t = e >> 4, grp = e & 15;
            float4 a = *(const float4*)(attB + (size_t)t * 64 + grp * 4);
            *(uint4*)&As[t][grp * 4] =
                make_uint4(cvt_tf32(a.x), cvt_tf32(a.y), cvt_tf32(a.z), cvt_tf32(a.w));
        }
        CP_WAIT0();
        __syncthreads();

        #pragma unroll
        for (int g8 = 0; g8 < 8; g8++) {
            unsigned a[4];
            a[0] = __float_as_uint(As[g8 * 8 + kc    ][m0 + lr    ]);
            a[1] = __float_as_uint(As[g8 * 8 + kc    ][m0 + lr + 8]);
            a[2] = __float_as_uint(As[g8 * 8 + kc + 4][m0 + lr    ]);
            a[3] = __float_as_uint(As[g8 * 8 + kc + 4][m0 + lr + 8]);
            #pragma unroll
            for (int j = 0; j < 13; j++) {
                unsigned b[2];
                b[0] = __float_as_uint(Bs[g8 * 8 + kc    ][nb0 + 8 * j + lr]);
                b[1] = __float_as_uint(Bs[g8 * 8 + kc + 4][nb0 + 8 * j + lr]);
                mma8(acc[j], a, b);
            }
        }
        __syncthreads();
    }

    const float sbn = on_g[cch] * rsqrtf(on_v[cch] + 1e-5f);
    const float sh  = on_bb[cch] - on_m[cch] * sbn + on_b[cch] * sbn;
    const float* gres = g + ((size_t)n * Cc + cch) * Pp;
    float* zb = out + ((size_t)n * Cc + cch) * Pp;

    #pragma unroll
    for (int half = 0; half < 2; half++) {
        int q = m0 + lr + half * 8;
        #pragma unroll
        for (int j = 0; j < 13; j++) {
            int v = nb0 + 8 * j + 2 * kc;
            if (v < 204) {
                float2 rv = *(const float2*)(gres + (size_t)q * 204 + v);
                float va = acc[j][half * 2]     * sbn + sh + rv.x;
                float vb = acc[j][half * 2 + 1] * sbn + sh + rv.y;
                *(float2*)(zb + (size_t)q * 204 + v) =
                    make_float2(va > 0.f ? va : 0.1f * va, vb > 0.f ? vb : 0.1f * vb);
            }
        }
    }
}

// ---------------- weight permute for G2: W2[s*64+c][cc] = on_w[c][s*64+cc] ----------------
__global__ void w2_permute(const float* __restrict__ on_w, float* __restrict__ W2)
{
    int idx = blockIdx.x * blockDim.x + threadIdx.x;
    if (idx >= HC * Cc) return;
    int o = idx >> 6, cc = idx & 63;
    int s = o >> 6, c = o & 63;
    W2[(size_t)o * Cc + cc] = on_w[(size_t)c * HC + s * 64 + cc];
}

// ============================================================================
// attention (fp32): split-K partials + combine
// ============================================================================
__global__ __launch_bounds__(256)
void attn_partial_kernel(const float* __restrict__ qk, float* __restrict__ part)
{
    __shared__ float Qs[32][68];
    __shared__ float Ks[32][68];

    const int hh = blockIdx.x;
    const int n  = blockIdx.y;
    const int z  = blockIdx.z;
    const int c0 = z * 8;
    const int tid = threadIdx.x;
    const int t0 = (tid >> 4) * 4;
    const int q0 = (tid & 15) * 4;

    const float* qb = qk + ((size_t)n * OQKV + hh * QKd) * Pp;
    const float* kb = qk + ((size_t)n * OQKV + Hh * QKd + hh * QKd) * Pp;

    float acc[4][4] = {};

    for (int c = c0; c < c0 + 8; c++) {
        for (int vb = 0; vb < Vv; vb += 32) {
            #pragma unroll
            for (int i = 0; i < 8; i++) {
                int e  = tid + 256 * i;
                int vv = e & 31;
                int t  = e >> 5;
                int v  = vb + vv;
                bool ok = (v < Vv);
                Qs[vv][t] = ok ? qb[(size_t)c * Pp + t * Vv + v] : 0.f;
                Ks[vv][t] = ok ? kb[(size_t)c * Pp + t * Vv + v] : 0.f;
            }
            __syncthreads();
            #pragma unroll
            for (int vv = 0; vv < 32; vv++) {
                float4 qv = *(const float4*)&Qs[vv][t0];
                float4 kv = *(const float4*)&Ks[vv][q0];
                float qq[4] = {qv.x, qv.y, qv.z, qv.w};
                float kk[4] = {kv.x, kv.y, kv.z, kv.w};
                #pragma unroll
                for (int i = 0; i < 4; i++)
                    #pragma unroll
                    for (int j = 0; j < 4; j++)
                        acc[i][j] = fmaf(qq[i], kk[j], acc[i][j]);
            }
            __syncthreads();
        }
    }

    float* pb = part + (((size_t)z * Nn + n) * Hh + hh) * (Tt * Tt);
    #pragma unroll
    for (int i = 0; i < 4; i++)
        #pragma unroll
        for (int j = 0; j < 4; j++)
            pb[(size_t)(t0 + i) * Tt + q0 + j] = acc[i][j];
}

__global__ void attn_combine_kernel(const float* __restrict__ part,
                                    const float* __restrict__ alphas,
                                    const float* __restrict__ att1s,
                                    float* __restrict__ att)
{
    int idx = blockIdx.x * blockDim.x + threadIdx.x;
    const int total = Nn * Hh * Tt * Tt;
    if (idx >= total) return;
    int tq = idx & (Tt * Tt - 1);
    int h  = (idx / (Tt * Tt)) % Hh;
    float p = part[idx] + part[(size_t)total + idx];
    const float inv = 1.0f / (float)(QKd * Vv);
    att[idx] = tanhf(p * inv) * alphas[h] + att1s[(size_t)h * Tt * Tt + tq];
}

// ---------------- launch ----------------
extern "C" void kernel_launch(void* const* d_in, const int* in_sizes, int n_in,
                              void* d_out, int out_size)
{
    const float* x      = (const float*)d_in[0];
    const float* A      = (const float*)d_in[1];
    const float* gcn_w  = (const float*)d_in[2];
    const float* gcn_b  = (const float*)d_in[3];
    const float* gcn_g  = (const float*)d_in[4];
    const float* gcn_bb = (const float*)d_in[5];
    const float* gcn_m  = (const float*)d_in[6];
    const float* gcn_v  = (const float*)d_in[7];
    const float* pe     = (const float*)d_in[8];
    const float* qkv_w  = (const float*)d_in[9];
    const float* qkv_b  = (const float*)d_in[10];
    const float* alphas = (const float*)d_in[11];
    const float* att1s  = (const float*)d_in[12];
    const float* on_w   = (const float*)d_in[13];
    const float* on_b   = (const float*)d_in[14];
    const float* on_g   = (const float*)d_in[15];
    const float* on_bb  = (const float*)d_in[16];
    const float* on_m   = (const float*)d_in[17];
    const float* on_v   = (const float*)d_in[18];
    const float* ff_w   = (const float*)d_in[19];
    const float* ff_b   = (const float*)d_in[20];
    const float* ff_g   = (const float*)d_in[21];
    const float* ff_bb  = (const float*)d_in[22];
    const float* ff_m   = (const float*)d_in[23];
    const float* ff_v   = (const float*)d_in[24];
    float* out = (float*)d_out;

    float *ph, *pg, *pqk, *pwpe, *patt, *pattp, *pG2, *pw2;
    cudaGetSymbolAddress((void**)&ph,    d_h);
    cudaGetSymbolAddress((void**)&pg,    d_g);
    cudaGetSymbolAddress((void**)&pqk,   d_qk);
    cudaGetSymbolAddress((void**)&pwpe,  d_wpe);
    cudaGetSymbolAddress((void**)&patt,  d_att);
    cudaGetSymbolAddress((void**)&pattp, d_attp);
    cudaGetSymbolAddress((void**)&pG2,   d_G2);
    cudaGetSymbolAddress((void**)&pw2,   d_w2);

    static int smem_set = 0;
    const int zsmem = (64 * 72 + 64 * 232) * 4;
    if (!smem_set) {
        cudaFuncSetAttribute(z_mma, cudaFuncAttributeMaxDynamicSharedMemorySize, zsmem);
        smem_set = 1;
    }

    dim3 blk(256);

    // K0: wpe = qkv_w @ pe + qkv_b ; also permute on_w
    w2_permute<<<(HC * Cc + 255) / 256, blk>>>(on_w, pw2);
    conv_mma<MODE_BIAS><<<dim3(Pp / 256, 2, 1), blk>>>(
        pe, qkv_w, qkv_b, nullptr, nullptr, nullptr, nullptr, nullptr, nullptr,
        pwpe, Cc, OQKV);

    // K1: h = gcn conv
    conv_mma<MODE_BIAS><<<dim3(Pp / 256, 1, Nn), blk>>>(
        x, gcn_w, gcn_b, nullptr, nullptr, nullptr, nullptr, nullptr, nullptr,
        ph, Cc, Cc);

    // K2: g = relu(bn(A @ h) + x)
    adj_mma<<<dim3((Nn * Cc * Tt) / 64, 1, 1), blk>>>(
        ph, A, x, gcn_g, gcn_bb, gcn_m, gcn_v, pg);

    // K3: qk = qkv_w @ g + wpe
    conv_mma<MODE_ADD2D><<<dim3(Pp / 256, 2, Nn), blk>>>(
        pg, qkv_w, nullptr, pwpe, nullptr, nullptr, nullptr, nullptr, nullptr,
        pqk, Cc, OQKV);

    // K4: attention scores + combine
    attn_partial_kernel<<<dim3(Hh, Nn, 2), blk>>>(pqk, pattp);
    attn_combine_kernel<<<(Nn * Hh * Tt * Tt + 255) / 256, blk>>>(pattp, alphas, att1s, patt);

    // K5: G2[n,(s,c),p] = sum_cc W2[(s,c),cc] * g[n,cc,p]
    conv_mma<MODE_NONE><<<dim3(Pp / 256, 3, Nn), blk>>>(
        pg, pw2, nullptr, nullptr, nullptr, nullptr, nullptr, nullptr, nullptr,
        pG2, Cc, HC);

    // K6: z = leaky(bn(sum_{s,t} G2*att + on_b) + g)  -> d_h
    z_mma<<<dim3(Cc, Nn), blk, zsmem>>>(
        pG2, patt, pg, on_b, on_g, on_bb, on_m, on_v, ph);

    // K7: out = leaky(bn(ff_w @ z + ff_b) + g)
    conv_mma<MODE_BN_RES_LEAKY><<<dim3(Pp / 256, 1, Nn), blk>>>(
        ph, ff_w, ff_b, nullptr, pg, ff_g, ff_bb, ff_m, ff_v,
        out, Cc, Cc);
}

// round 5
// speedup vs baseline: 1.3705x; 1.3705x over previous
#include <cuda_runtime.h>
#include <math.h>
#include <stdint.h>

// Problem constants
#define Nn   32
#define Cc   64
#define Tt   64
#define Vv   204
#define Hh   3
#define QKd  16
#define Pp   13056
#define OQKV 96
#define HC   192

// ---------------- scratch (padded where edge chunks over-read) ----------------
__device__ float d_h   [(size_t)Nn * Cc * Pp + 64];   // gcn conv out; later z
__device__ float d_g   [(size_t)Nn * Cc * Pp + 64];
__device__ float d_qk  [(size_t)Nn * OQKV * Pp + 64];
__device__ float d_wpe [(size_t)OQKV * Pp];
__device__ float d_att [(size_t)Nn * Hh * Tt * Tt];
__device__ float d_attp[(size_t)4 * Nn * Hh * Tt * Tt];
__device__ float d_G2  [(size_t)Nn * HC * Pp + 64];
__device__ float d_wt  [4096 + 6144 + 4096 + 12288];  // tf32: gcn | qkv | ff | w2(permuted on_w)
__device__ float d_A2  [208 * 208];                   // tf32 zero-padded adjacency [u][v]

#define WT_GCN 0
#define WT_QKV 4096
#define WT_FF  10240
#define WT_W2  14336

enum { MODE_BIAS = 0, MODE_ADD2D = 1, MODE_BN_RES_LEAKY = 2, MODE_NONE = 3 };

// ---------------- helpers ----------------
__device__ __forceinline__ unsigned cvt_tf32(float f) {
    unsigned u;
    asm("cvt.rna.tf32.f32 %0, %1;" : "=r"(u) : "f"(f));
    return u;
}
__device__ __forceinline__ float rna_f(float f) { return __uint_as_float(cvt_tf32(f)); }

__device__ __forceinline__ void mma8(float* d, const unsigned* a, const unsigned* b) {
    asm volatile(
        "mma.sync.aligned.m16n8k8.row.col.f32.tf32.tf32.f32 "
        "{%0,%1,%2,%3},{%4,%5,%6,%7},{%8,%9},{%0,%1,%2,%3};"
        : "+f"(d[0]), "+f"(d[1]), "+f"(d[2]), "+f"(d[3])
        : "r"(a[0]), "r"(a[1]), "r"(a[2]), "r"(a[3]), "r"(b[0]), "r"(b[1]));
}

__device__ __forceinline__ uint32_t smem_u32(const void* p) {
    return (uint32_t)__cvta_generic_to_shared(p);
}
__device__ __forceinline__ void cpa16(uint32_t dst, const void* src) {
    asm volatile("cp.async.cg.shared.global [%0],[%1],16;" :: "r"(dst), "l"(src));
}
__device__ __forceinline__ void cpa16z(uint32_t dst, const void* src, int sz) {
    asm volatile("cp.async.cg.shared.global [%0],[%1],16,%2;" :: "r"(dst), "l"(src), "r"(sz));
}
#define CP_COMMIT() asm volatile("cp.async.commit_group;")
#define CP_WAIT2()  asm volatile("cp.async.wait_group 2;")

// ============================================================================
// prep: tf32-convert all small operands once per call
// ============================================================================
__global__ void prep_kernel(const float* __restrict__ gcn_w, const float* __restrict__ qkv_w,
                            const float* __restrict__ ff_w, const float* __restrict__ on_w,
                            const float* __restrict__ A,
                            float* __restrict__ wt, float* __restrict__ A2)
{
    int i = blockIdx.x * 256 + threadIdx.x;
    if (i < 4096) { wt[WT_GCN + i] = rna_f(gcn_w[i]); return; }
    i -= 4096;
    if (i < 6144) { wt[WT_QKV + i] = rna_f(qkv_w[i]); return; }
    i -= 6144;
    if (i < 4096) { wt[WT_FF + i] = rna_f(ff_w[i]); return; }
    i -= 4096;
    if (i < 12288) {
        int o = i >> 6, cc = i & 63;
        int s = o >> 6, c = o & 63;
        wt[WT_W2 + i] = rna_f(on_w[(size_t)c * HC + s * 64 + cc]);
        return;
    }
    i -= 12288;
    if (i < 208 * 208) {
        int u = i / 208, v = i % 208;
        A2[i] = (u < 204 && v < 204) ? rna_f(A[(size_t)u * 204 + v]) : 0.f;
    }
}

// ============================================================================
// conv_mma: out[n,o,p] = sum_c W[o,c]*in[n,c,p]
// M=64(Oc tile), N=256(P), k-chunk 16 (Kc=64 -> 4 chunks), 4-stage ring, 1 sync/chunk.
// ============================================================================
#define CV_ASZ (64 * 20)
#define CV_BSZ (16 * 264)
#define CV_SMEM (4 * (CV_ASZ + CV_BSZ) * 4)

template <int MODE, int ROUND>
__global__ __launch_bounds__(256, 2)
void conv_mma(const float* __restrict__ in, const float* __restrict__ Wt,
              const float* __restrict__ bias, const float* __restrict__ add2d,
              const float* __restrict__ res,
              const float* __restrict__ bng, const float* __restrict__ bnb,
              const float* __restrict__ bnm, const float* __restrict__ bnv,
              float* __restrict__ out, int Kc, int Oc)
{
    extern __shared__ float sm[];
    float* As = sm;                 // 4 stages of [64][20]
    float* Bs = sm + 4 * CV_ASZ;    // 4 stages of [16][264]

    const int n  = blockIdx.z;
    const int pt = blockIdx.x * 256;
    const int ot = blockIdx.y * 64;
    const int tid = threadIdx.x, lane = tid & 31, warp = tid >> 5;
    const int wm = warp & 1, wn = warp >> 1;
    const int m0 = wm * 32, n0 = wn * 64;
    const int lr = lane >> 2, kc = lane & 3;

    const float* inN = in + (size_t)n * Kc * Pp + pt;
    const int arow = tid >> 2, agrp = tid & 3;
    const int NCH = Kc >> 4;

    float acc[2][8][4];
    #pragma unroll
    for (int f = 0; f < 2; f++)
        #pragma unroll
        for (int j = 0; j < 8; j++)
            #pragma unroll
            for (int q = 0; q < 4; q++) acc[f][j][q] = 0.f;

    // prefetch chunk c into stage
    auto prefetch = [&](int c, int stage) {
        float* BsS = Bs + stage * CV_BSZ;
        const float* bsrc = inN + (size_t)(c * 16) * Pp;
        #pragma unroll
        for (int i = 0; i < 4; i++) {
            int e = tid + 256 * i;
            int k = e >> 6, grp = e & 63;
            cpa16(smem_u32(&BsS[k * 264 + grp * 4]), bsrc + (size_t)k * Pp + grp * 4);
        }
        float* AsS = As + stage * CV_ASZ;
        int o = ot + arow;
        int ok = (o < Oc);
        cpa16z(smem_u32(&AsS[arow * 20 + agrp * 4]),
               ok ? (Wt + (size_t)o * Kc + c * 16 + agrp * 4) : Wt, ok ? 16 : 0);
    };

    prefetch(0, 0); CP_COMMIT();
    if (NCH > 1) prefetch(1, 1);
    CP_COMMIT();

    for (int c = 0; c < NCH; c++) {
        if (c + 2 < NCH) prefetch(c + 2, (c + 2) & 3);
        CP_COMMIT();
        CP_WAIT2();
        __syncthreads();

        const float* AsS = As + (c & 3) * CV_ASZ;
        const float* BsS = Bs + (c & 3) * CV_BSZ;
        #pragma unroll
        for (int g = 0; g < 2; g++) {
            unsigned a[2][4];
            #pragma unroll
            for (int f = 0; f < 2; f++) {
                a[f][0] = __float_as_uint(AsS[(m0 + f * 16 + lr    ) * 20 + g * 8 + kc    ]);
                a[f][1] = __float_as_uint(AsS[(m0 + f * 16 + lr + 8) * 20 + g * 8 + kc    ]);
                a[f][2] = __float_as_uint(AsS[(m0 + f * 16 + lr    ) * 20 + g * 8 + kc + 4]);
                a[f][3] = __float_as_uint(AsS[(m0 + f * 16 + lr + 8) * 20 + g * 8 + kc + 4]);
            }
            #pragma unroll
            for (int j = 0; j < 8; j++) {
                unsigned b[2];
                b[0] = __float_as_uint(BsS[(g * 8 + kc    ) * 264 + n0 + 8 * j + lr]);
                b[1] = __float_as_uint(BsS[(g * 8 + kc + 4) * 264 + n0 + 8 * j + lr]);
                mma8(acc[0][j], a[0], b);
                mma8(acc[1][j], a[1], b);
            }
        }
    }

    #pragma unroll
    for (int f = 0; f < 2; f++) {
        #pragma unroll
        for (int half = 0; half < 2; half++) {
            int o = ot + m0 + f * 16 + lr + half * 8;
            if (o >= Oc) continue;
            size_t obase = ((size_t)n * Oc + o) * Pp;
            if (MODE == MODE_NONE) {
                #pragma unroll
                for (int j = 0; j < 8; j++) {
                    int p = pt + n0 + 8 * j + 2 * kc;
                    float va = acc[f][j][half * 2], vb = acc[f][j][half * 2 + 1];
                    if (ROUND) { va = rna_f(va); vb = rna_f(vb); }
                    *(float2*)(out + obase + p) = make_float2(va, vb);
                }
            } else if (MODE == MODE_BIAS) {
                float b = bias[o];
                #pragma unroll
                for (int j = 0; j < 8; j++) {
                    int p = pt + n0 + 8 * j + 2 * kc;
                    float va = acc[f][j][half * 2] + b, vb = acc[f][j][half * 2 + 1] + b;
                    if (ROUND) { va = rna_f(va); vb = rna_f(vb); }
                    *(float2*)(out + obase + p) = make_float2(va, vb);
                }
            } else if (MODE == MODE_ADD2D) {
                size_t abase = (size_t)o * Pp;
                #pragma unroll
                for (int j = 0; j < 8; j++) {
                    int p = pt + n0 + 8 * j + 2 * kc;
                    float2 av = *(const float2*)(add2d + abase + p);
                    float va = acc[f][j][half * 2] + av.x, vb = acc[f][j][half * 2 + 1] + av.y;
                    if (ROUND) { va = rna_f(va); vb = rna_f(vb); }
                    *(float2*)(out + obase + p) = make_float2(va, vb);
                }
            } else { // MODE_BN_RES_LEAKY
                float s  = bng[o] * rsqrtf(bnv[o] + 1e-5f);
                float sh = bnb[o] - bnm[o] * s + bias[o] * s;
                #pragma unroll
                for (int j = 0; j < 8; j++) {
                    int p = pt + n0 + 8 * j + 2 * kc;
                    float2 rv = *(const float2*)(res + obase + p);
                    float va = acc[f][j][half * 2]     * s + sh + rv.x;
                    float vb = acc[f][j][half * 2 + 1] * s + sh + rv.y;
                    va = (va > 0.f) ? va : 0.1f * va;
                    vb = (vb > 0.f) ? vb : 0.1f * vb;
                    if (ROUND) { va = rna_f(va); vb = rna_f(vb); }
                    *(float2*)(out + obase + p) = make_float2(va, vb);
                }
            }
        }
    }
}

// ============================================================================
// adj_mma: g[r,u] = relu(bn_c(sum_v h[r,v]*A2[u,v]) + x[r,u])
// M=64(r), N=208(u), K=208 padded (13 chunks of 16), 4-stage ring.
// ============================================================================
#define AD_ASZ (64 * 20)
#define AD_BSZ (208 * 20)
#define AD_SMEM (4 * (AD_ASZ + AD_BSZ) * 4)

__global__ __launch_bounds__(256, 2)
void adj_mma(const float* __restrict__ h, const float* __restrict__ A2,
             const float* __restrict__ x,
             const float* __restrict__ bng, const float* __restrict__ bnb,
             const float* __restrict__ bnm, const float* __restrict__ bnv,
             float* __restrict__ out)
{
    extern __shared__ float sm[];
    float* As = sm;                 // 4 stages of [64][20]   (h rows)
    float* Bs = sm + 4 * AD_ASZ;    // 4 stages of [208][20]  (A2 rows)

    const int rt = blockIdx.x * 64;
    const int tid = threadIdx.x, lane = tid & 31, warp = tid >> 5;
    const int wm = warp & 3, wn = warp >> 2;
    const int m0 = wm * 16, nb0 = wn * 104;
    const int lr = lane >> 2, kc = lane & 3;

    const int ch  = (rt >> 6) & 63;
    const float s  = bng[ch] * rsqrtf(bnv[ch] + 1e-5f);
    const float sh = bnb[ch] - bnm[ch] * s;

    float acc[13][4];
    #pragma unroll
    for (int j = 0; j < 13; j++)
        #pragma unroll
        for (int q = 0; q < 4; q++) acc[j][q] = 0.f;

    const int arow = tid >> 2, agrp = tid & 3;
    const int NCH = 13;

    auto prefetch = [&](int c, int stage) {
        float* BsS = Bs + stage * AD_BSZ;
        #pragma unroll
        for (int i = 0; i < 4; i++) {
            int e = tid + 256 * i;
            if (e < 832) {
                int u = e >> 2, grp = e & 3;
                cpa16(smem_u32(&BsS[u * 20 + grp * 4]), A2 + (size_t)u * 208 + c * 16 + grp * 4);
            }
        }
        float* AsS = As + stage * AD_ASZ;
        cpa16(smem_u32(&AsS[arow * 20 + agrp * 4]),
              h + (size_t)(rt + arow) * 204 + c * 16 + agrp * 4);  // edge over-read hits A2 zero k-rows
    };

    prefetch(0, 0); CP_COMMIT();
    prefetch(1, 1); CP_COMMIT();

    for (int c = 0; c < NCH; c++) {
        if (c + 2 < NCH) prefetch(c + 2, (c + 2) & 3);
        CP_COMMIT();
        CP_WAIT2();
        __syncthreads();

        const float* AsS = As + (c & 3) * AD_ASZ;
        const float* BsS = Bs + (c & 3) * AD_BSZ;
        #pragma unroll
        for (int g = 0; g < 2; g++) {
            unsigned a[4];
            a[0] = __float_as_uint(AsS[(m0 + lr    ) * 20 + g * 8 + kc    ]);
            a[1] = __float_as_uint(AsS[(m0 + lr + 8) * 20 + g * 8 + kc    ]);
            a[2] = __float_as_uint(AsS[(m0 + lr    ) * 20 + g * 8 + kc + 4]);
            a[3] = __float_as_uint(AsS[(m0 + lr + 8) * 20 + g * 8 + kc + 4]);
            #pragma unroll
            for (int j = 0; j < 13; j++) {
                unsigned b[2];
                b[0] = __float_as_uint(BsS[(nb0 + 8 * j + lr) * 20 + g * 8 + kc    ]);
                b[1] = __float_as_uint(BsS[(nb0 + 8 * j + lr) * 20 + g * 8 + kc + 4]);
                mma8(acc[j], a, b);
            }
        }
    }

    #pragma unroll
    for (int half = 0; half < 2; half++) {
        int r = rt + m0 + lr + half * 8;
        size_t rbase = (size_t)r * 204;
        #pragma unroll
        for (int j = 0; j < 13; j++) {
            int u = nb0 + 8 * j + 2 * kc;
            if (u < 204) {
                float2 xv = *(const float2*)(x + rbase + u);
                float va = acc[j][half * 2]     * s + sh + xv.x;
                float vb = acc[j][half * 2 + 1] * s + sh + xv.y;
                *(float2*)(out + rbase + u) =
                    make_float2(rna_f(fmaxf(va, 0.f)), rna_f(fmaxf(vb, 0.f)));
            }
        }
    }
}

// ============================================================================
// attn_mma: part[z,n,h,t,q] = sum_{c in 4-chunk z, v} q[c,t,v]*k[c,q,v]   (tf32)
// M=64(t), N=64(q), K=4x204 padded -> 52 chunks of 16. grid (3,32,4).
// ============================================================================
#define AT_QSZ (64 * 20)
#define AT_SMEM (4 * 2 * AT_QSZ * 4)

__global__ __launch_bounds__(256, 3)
void attn_mma(const float* __restrict__ qk, float* __restrict__ part)
{
    extern __shared__ float sm[];
    float* Qs = sm;                 // 4 stages [t=64][k=16]
    float* Ks = sm + 4 * AT_QSZ;    // 4 stages [q=64][k=16]

    const int hh = blockIdx.x, n = blockIdx.y, z = blockIdx.z;
    const int cc0 = z * 4;
    const int tid = threadIdx.x, lane = tid & 31, warp = tid >> 5;
    const int wm = warp & 3, wn = warp >> 2;
    const int m0 = wm * 16, nb0 = wn * 32;
    const int lr = lane >> 2, kc = lane & 3;

    const float* qbase = qk + ((size_t)n * OQKV + hh * QKd) * Pp;
    const float* kbase = qk + ((size_t)n * OQKV + Hh * QKd + hh * QKd) * Pp;

    const int arow = tid >> 2, agrp = tid & 3;
    const int NCH = 52;

    float acc[4][4];
    #pragma unroll
    for (int j = 0; j < 4; j++)
        #pragma unroll
        for (int q = 0; q < 4; q++) acc[j][q] = 0.f;

    auto prefetch = [&](int c, int stage) {
        int ci = cc0 + (c / 13);
        int vb = (c % 13) * 16;
        int v = vb + agrp * 4;
        int ok = (v < 204);
        const float* qs = qbase + (size_t)ci * Pp + (size_t)arow * 204 + v;
        const float* ks = kbase + (size_t)ci * Pp + (size_t)arow * 204 + v;
        cpa16z(smem_u32(&Qs[stage * AT_QSZ + arow * 20 + agrp * 4]), ok ? qs : qk, ok ? 16 : 0);
        cpa16z(smem_u32(&Ks[stage * AT_QSZ + arow * 20 + agrp * 4]), ok ? ks : qk, ok ? 16 : 0);
    };

    prefetch(0, 0); CP_COMMIT();
    prefetch(1, 1); CP_COMMIT();

    for (int c = 0; c < NCH; c++) {
        if (c + 2 < NCH) prefetch(c + 2, (c + 2) & 3);
        CP_COMMIT();
        CP_WAIT2();
        __syncthreads();

        const float* QsS = Qs + (c & 3) * AT_QSZ;
        const float* KsS = Ks + (c & 3) * AT_QSZ;
        #pragma unroll
        for (int g = 0; g < 2; g++) {
            unsigned a[4];
            a[0] = __float_as_uint(QsS[(m0 + lr    ) * 20 + g * 8 + kc    ]);
            a[1] = __float_as_uint(QsS[(m0 + lr + 8) * 20 + g * 8 + kc    ]);
            a[2] = __float_as_uint(QsS[(m0 + lr    ) * 20 + g * 8 + kc + 4]);
            a[3] = __float_as_uint(QsS[(m0 + lr + 8) * 20 + g * 8 + kc + 4]);
            #pragma unroll
            for (int j = 0; j < 4; j++) {
                unsigned b[2];
                b[0] = __float_as_uint(KsS[(nb0 + 8 * j + lr) * 20 + g * 8 + kc    ]);
                b[1] = __float_as_uint(KsS[(nb0 + 8 * j + lr) * 20 + g * 8 + kc + 4]);
                mma8(acc[j], a, b);
            }
        }
    }

    float* pb = part + (((size_t)z * Nn + n) * Hh + hh) * 4096;
    #pragma unroll
    for (int half = 0; half < 2; half++) {
        int t = m0 + lr + half * 8;
        #pragma unroll
        for (int j = 0; j < 4; j++) {
            int q = nb0 + 8 * j + 2 * kc;
            *(float2*)(pb + (size_t)t * 64 + q) =
                make_float2(acc[j][half * 2], acc[j][half * 2 + 1]);
        }
    }
}

__global__ void attn_combine_kernel(const float* __restrict__ part,
                                    const float* __restrict__ alphas,
                                    const float* __restrict__ att1s,
                                    float* __restrict__ att)
{
    int idx = blockIdx.x * blockDim.x + threadIdx.x;
    const int total = Nn * Hh * Tt * Tt;
    if (idx >= total) return;
    int tq = idx & (Tt * Tt - 1);
    int h  = (idx / (Tt * Tt)) % Hh;
    float p = part[idx] + part[(size_t)total + idx]
            + part[2 * (size_t)total + idx] + part[3 * (size_t)total + idx];
    const float inv = 1.0f / (float)(QKd * Vv);
    att[idx] = rna_f(tanhf(p * inv) * alphas[h] + att1s[(size_t)h * Tt * Tt + tq]);
}

// ============================================================================
// z_mma: z[n,c,q,v] = leaky(bn_c(sum_{s,t} G2[n,s,c,t,v]*att[n,s,t,q]) + g)
// M=64(q), N=208(v), K=192 (12 chunks of 16 t), 4-stage ring. grid (64,32).
// ============================================================================
#define ZM_ASZ (16 * 72)
#define ZM_BSZ (16 * 212)
#define ZM_SMEM (4 * (ZM_ASZ + ZM_BSZ) * 4)

__global__ __launch_bounds__(256, 2)
void z_mma(const float* __restrict__ G2, const float* __restrict__ att,
           const float* __restrict__ g,
           const float* __restrict__ on_b, const float* __restrict__ on_g,
           const float* __restrict__ on_bb, const float* __restrict__ on_m,
           const float* __restrict__ on_v,
           float* __restrict__ out)
{
    extern __shared__ float sm[];
    float* As = sm;                 // 4 stages [t=16][q=64(+pad)]  att
    float* Bs = sm + 4 * ZM_ASZ;    // 4 stages [t=16][v=208(+pad)] G2

    const int cch = blockIdx.x, n = blockIdx.y;
    const int tid = threadIdx.x, lane = tid & 31, warp = tid >> 5;
    const int wm = warp & 3, wn = warp >> 2;
    const int m0 = wm * 16, nb0 = wn * 104;
    const int lr = lane >> 2, kc = lane & 3;

    float acc[13][4];
    #pragma unroll
    for (int j = 0; j < 13; j++)
        #pragma unroll
        for (int q = 0; q < 4; q++) acc[j][q] = 0.f;

    const int NCH = 12;

    auto prefetch = [&](int c, int stage) {
        int s  = c >> 2;
        int tb = (c & 3) * 16;
        const float* gb = G2 + ((size_t)n * HC + s * 64 + cch) * Pp;
        float* BsS = Bs + stage * ZM_BSZ;
        #pragma unroll
        for (int i = 0; i < 4; i++) {
            int e = tid + 256 * i;
            if (e < 832) {
                int trow = e / 52, grp = e % 52;
                int ok = (grp < 51);
                cpa16z(smem_u32(&BsS[trow * 212 + grp * 4]),
                       ok ? (gb + (size_t)(tb + trow) * 204 + grp * 4) : gb, ok ? 16 : 0);
            }
        }
        float* AsS = As + stage * ZM_ASZ;
        int trow = tid >> 4, grp = tid & 15;
        cpa16(smem_u32(&AsS[trow * 72 + grp * 4]),
              att + ((size_t)(n * Hh + s)) * 4096 + (size_t)(tb + trow) * 64 + grp * 4);
    };

    prefetch(0, 0); CP_COMMIT();
    prefetch(1, 1); CP_COMMIT();

    for (int c = 0; c < NCH; c++) {
        if (c + 2 < NCH) prefetch(c + 2, (c + 2) & 3);
        CP_COMMIT();
        CP_WAIT2();
        __syncthreads();

        const float* AsS = As + (c & 3) * ZM_ASZ;
        const float* BsS = Bs + (c & 3) * ZM_BSZ;
        #pragma unroll
        for (int g8 = 0; g8 < 2; g8++) {
            unsigned a[4];
            a[0] = __float_as_uint(AsS[(g8 * 8 + kc    ) * 72 + m0 + lr    ]);
            a[1] = __float_as_uint(AsS[(g8 * 8 + kc    ) * 72 + m0 + lr + 8]);
            a[2] = __float_as_uint(AsS[(g8 * 8 + kc + 4) * 72 + m0 + lr    ]);
            a[3] = __float_as_uint(AsS[(g8 * 8 + kc + 4) * 72 + m0 + lr + 8]);
            #pragma unroll
            for (int j = 0; j < 13; j++) {
                unsigned b[2];
                b[0] = __float_as_uint(BsS[(g8 * 8 + kc    ) * 212 + nb0 + 8 * j + lr]);
                b[1] = __float_as_uint(BsS[(g8 * 8 + kc + 4) * 212 + nb0 + 8 * j + lr]);
                mma8(acc[j], a, b);
            }
        }
    }

    const float sbn = on_g[cch] * rsqrtf(on_v[cch] + 1e-5f);
    const float sh  = on_bb[cch] - on_m[cch] * sbn + on_b[cch] * sbn;
    const float* gres = g + ((size_t)n * Cc + cch) * Pp;
    float* zb = out + ((size_t)n * Cc + cch) * Pp;

    #pragma unroll
    for (int half = 0; half < 2; half++) {
        int q = m0 + lr + half * 8;
        #pragma unroll
        for (int j = 0; j < 13; j++) {
            int v = nb0 + 8 * j + 2 * kc;
            if (v < 204) {
                float2 rv = *(const float2*)(gres + (size_t)q * 204 + v);
                float va = acc[j][half * 2]     * sbn + sh + rv.x;
                float vb = acc[j][half * 2 + 1] * sbn + sh + rv.y;
                va = (va > 0.f) ? va : 0.1f * va;
                vb = (vb > 0.f) ? vb : 0.1f * vb;
                *(float2*)(zb + (size_t)q * 204 + v) = make_float2(rna_f(va), rna_f(vb));
            }
        }
    }
}

// ---------------- launch ----------------
extern "C" void kernel_launch(void* const* d_in, const int* in_sizes, int n_in,
                              void* d_out, int out_size)
{
    const float* x      = (const float*)d_in[0];
    const float* A      = (const float*)d_in[1];
    const float* gcn_w  = (const float*)d_in[2];
    const float* gcn_b  = (const float*)d_in[3];
    const float* gcn_g  = (const float*)d_in[4];
    const float* gcn_bb = (const float*)d_in[5];
    const float* gcn_m  = (const float*)d_in[6];
    const float* gcn_v  = (const float*)d_in[7];
    const float* pe     = (const float*)d_in[8];
    const float* qkv_w  = (const float*)d_in[9];
    const float* qkv_b  = (const float*)d_in[10];
    const float* alphas = (const float*)d_in[11];
    const float* att1s  = (const float*)d_in[12];
    const float* on_w   = (const float*)d_in[13];
    const float* on_b   = (const float*)d_in[14];
    const float* on_g   = (const float*)d_in[15];
    const float* on_bb  = (const float*)d_in[16];
    const float* on_m   = (const float*)d_in[17];
    const float* on_v   = (const float*)d_in[18];
    const float* ff_w   = (const float*)d_in[19];
    const float* ff_b   = (const float*)d_in[20];
    const float* ff_g   = (const float*)d_in[21];
    const float* ff_bb  = (const float*)d_in[22];
    const float* ff_m   = (const float*)d_in[23];
    const float* ff_v   = (const float*)d_in[24];
    float* out = (float*)d_out;

    float *ph, *pg, *pqk, *pwpe, *patt, *pattp, *pG2, *pwt, *pA2;
    cudaGetSymbolAddress((void**)&ph,    d_h);
    cudaGetSymbolAddress((void**)&pg,    d_g);
    cudaGetSymbolAddress((void**)&pqk,   d_qk);
    cudaGetSymbolAddress((void**)&pwpe,  d_wpe);
    cudaGetSymbolAddress((void**)&patt,  d_att);
    cudaGetSymbolAddress((void**)&pattp, d_attp);
    cudaGetSymbolAddress((void**)&pG2,   d_G2);
    cudaGetSymbolAddress((void**)&pwt,   d_wt);
    cudaGetSymbolAddress((void**)&pA2,   d_A2);

    static int attr_set = 0;
    if (!attr_set) {
        cudaFuncSetAttribute(conv_mma<MODE_BIAS, 0>, cudaFuncAttributeMaxDynamicSharedMemorySize, CV_SMEM);
        cudaFuncSetAttribute(conv_mma<MODE_BIAS, 1>, cudaFuncAttributeMaxDynamicSharedMemorySize, CV_SMEM);
        cudaFuncSetAttribute(conv_mma<MODE_ADD2D, 1>, cudaFuncAttributeMaxDynamicSharedMemorySize, CV_SMEM);
        cudaFuncSetAttribute(conv_mma<MODE_NONE, 1>, cudaFuncAttributeMaxDynamicSharedMemorySize, CV_SMEM);
        cudaFuncSetAttribute(conv_mma<MODE_BN_RES_LEAKY, 0>, cudaFuncAttributeMaxDynamicSharedMemorySize, CV_SMEM);
        cudaFuncSetAttribute(adj_mma, cudaFuncAttributeMaxDynamicSharedMemorySize, AD_SMEM);
        cudaFuncSetAttribute(attn_mma, cudaFuncAttributeMaxDynamicSharedMemorySize, AT_SMEM);
        cudaFuncSetAttribute(z_mma, cudaFuncAttributeMaxDynamicSharedMemorySize, ZM_SMEM);
        attr_set = 1;
    }

    dim3 blk(256);

    // P0: tf32 pre-convert small operands
    prep_kernel<<<(4096 + 6144 + 4096 + 12288 + 208 * 208 + 255) / 256, blk>>>(
        gcn_w, qkv_w, ff_w, on_w, A, pwt, pA2);

    // K0: wpe = qkv_w @ pe + qkv_b        (no rounding; rounded after add in K3)
    conv_mma<MODE_BIAS, 0><<<dim3(Pp / 256, 2, 1), blk, CV_SMEM>>>(
        pe, pwt + WT_QKV, qkv_b, nullptr, nullptr, nullptr, nullptr, nullptr, nullptr,
        pwpe, Cc, OQKV);

    // K1: h = gcn conv (tf32-rounded at store for adj A-side)
    conv_mma<MODE_BIAS, 1><<<dim3(Pp / 256, 1, Nn), blk, CV_SMEM>>>(
        x, pwt + WT_GCN, gcn_b, nullptr, nullptr, nullptr, nullptr, nullptr, nullptr,
        ph, Cc, Cc);

    // K2: g = relu(bn(A @ h) + x)  (rounded at store)
    adj_mma<<<dim3((Nn * Cc * Tt) / 64, 1, 1), blk, AD_SMEM>>>(
        ph, pA2, x, gcn_g, gcn_bb, gcn_m, gcn_v, pg);

    // K3: qk = qkv_w @ g + wpe  (rounded at store for attention)
    conv_mma<MODE_ADD2D, 1><<<dim3(Pp / 256, 2, Nn), blk, CV_SMEM>>>(
        pg, pwt + WT_QKV, nullptr, pwpe, nullptr, nullptr, nullptr, nullptr, nullptr,
        pqk, Cc, OQKV);

    // K4: attention scores (tf32 mma, split-K 4) + combine (rounds att)
    attn_mma<<<dim3(Hh, Nn, 4), blk, AT_SMEM>>>(pqk, pattp);
    attn_combine_kernel<<<(Nn * Hh * Tt * Tt + 255) / 256, blk>>>(pattp, alphas, att1s, patt);

    // K5: G2 = W2 @ g  (rounded at store)
    conv_mma<MODE_NONE, 1><<<dim3(Pp / 256, 3, Nn), blk, CV_SMEM>>>(
        pg, pwt + WT_W2, nullptr, nullptr, nullptr, nullptr, nullptr, nullptr, nullptr,
        pG2, Cc, HC);

    // K6: z = leaky(bn(sum G2*att + on_b) + g) -> d_h  (rounded at store)
    z_mma<<<dim3(Cc, Nn), blk, ZM_SMEM>>>(
        pG2, patt, pg, on_b, on_g, on_bb, on_m, on_v, ph);

    // K7: out = leaky(bn(ff_w @ z + ff_b) + g)
    conv_mma<MODE_BN_RES_LEAKY, 0><<<dim3(Pp / 256, 1, Nn), blk, CV_SMEM>>>(
        ph, pwt + WT_FF, ff_b, nullptr, pg, ff_g, ff_bb, ff_m, ff_v,
        out, Cc, Cc);
}